// round 15
// baseline (speedup 1.0000x reference)
#include <cuda_runtime.h>

#define B_  65536
#define T_  28
#define IN_ 28
#define HD_ 28
#define NC_ 10
#define NS  3          // samples per warp

typedef unsigned long long ull;

__device__ __forceinline__ ull pack2(float lo, float hi) {
    ull r; asm("mov.b64 %0, {%1, %2};" : "=l"(r) : "f"(lo), "f"(hi)); return r;
}
__device__ __forceinline__ void fma2(ull& acc, ull a, ull b) {
    asm("fma.rn.f32x2 %0, %1, %2, %0;" : "+l"(acc) : "l"(a), "l"(b));
}
__device__ __forceinline__ float hadd2(ull v) {
    float lo, hi; asm("mov.b64 {%0, %1}, %2;" : "=f"(lo), "=f"(hi) : "l"(v));
    return lo + hi;
}
__device__ __forceinline__ float tanh_a(float v) {
    float r; asm("tanh.approx.f32 %0, %1;" : "=f"(r) : "f"(v)); return r;
}
// sigmoid(2x) given pre-scaled input x = 0.5*logit (0.5 folded into weights)
__device__ __forceinline__ float sigm_pre(float v) {
    return fmaf(0.5f, tanh_a(v), 0.5f);
}

// encoder step: half-warp-split dot, gate-parallel, shuffle he handoff.
// Returns this lane's tracked unit value hn (lanes 0-3 = units 0-3).
__device__ __forceinline__ float enc_step(const ull (&ew)[8], ull ebp, int xoff,
                                          float eA, float eC, int u,
                                          const float* xrow,
                                          ull& he01, ull& he23, float& ce)
{
    const ulonglong2* xp = (const ulonglong2*)xrow + xoff;
    ulonglong2 v0 = xp[0], v1 = xp[1], v2 = xp[2], v3 = xp[3];
    ull o6 = xoff ? he01 : v3.x;
    ull o7 = xoff ? he23 : v3.y;
    ull acc0 = ebp;
    ull acc1 = 0ull;
    fma2(acc0, ew[0], v0.x); fma2(acc1, ew[1], v0.y);
    fma2(acc0, ew[2], v1.x); fma2(acc1, ew[3], v1.y);
    fma2(acc0, ew[4], v2.x); fma2(acc1, ew[5], v2.y);
    fma2(acc0, ew[6], o6);   fma2(acc1, ew[7], o7);
    float s = hadd2(acc0) + hadd2(acc1);
    s += __shfl_xor_sync(0xffffffffu, s, 16, 32);
    float gact = fmaf(eA, tanh_a(s), eC);      // sigm_pre or tanh per row
    float ai = __shfl_sync(0xffffffffu, gact, u,      32);
    float af = __shfl_sync(0xffffffffu, gact, u + 4,  32);
    float ag = __shfl_sync(0xffffffffu, gact, u + 8,  32);
    float ao = __shfl_sync(0xffffffffu, gact, u + 12, 32);
    float cen = af * ce + ai * ag;             // each lane tracks unit u = lane&3
    ce = cen;
    float hn = ao * tanh_a(cen);
    he01 = pack2(__shfl_sync(0xffffffffu, hn, 0, 32),
                 __shfl_sync(0xffffffffu, hn, 1, 32));
    he23 = pack2(__shfl_sync(0xffffffffu, hn, 2, 32),
                 __shfl_sync(0xffffffffu, hn, 3, 32));
    return hn;
}

// block = 128 threads = 4 warps = 12 samples (3 per warp).
// Phase 1: full encoder pass, he(t) -> smem. Phase 2: pure decoder loop.
__global__ void __launch_bounds__(128, 2)
ae_lstm_kernel(const float* __restrict__ x,
               const float* __restrict__ eWih, const float* __restrict__ eWhh,
               const float* __restrict__ eb,
               const float* __restrict__ dWih, const float* __restrict__ dWhh,
               const float* __restrict__ db,
               const float* __restrict__ uW,  const float* __restrict__ ubv,
               float* __restrict__ out, float* __restrict__ pred)
{
    __shared__ float sU[NC_ * HD_ + NC_];
    __shared__ __align__(16) float hbuf[4][NS][2][32];     // hd double buffer
    __shared__ __align__(16) float xbuf[4][NS][4][32];     // x ring (depth 4)
    __shared__ __align__(16) float shebuf[4][NS][T_ * 4];  // he(t) for all t

    for (int i = threadIdx.x; i < NC_ * HD_; i += blockDim.x) sU[i] = uW[i];
    for (int i = threadIdx.x; i < NC_;       i += blockDim.x) sU[NC_ * HD_ + i] = ubv[i];
    __syncthreads();

    const int lane = threadIdx.x & 31;
    const int w    = threadIdx.x >> 5;
    const int base = blockIdx.x * (4 * NS) + w * NS;

    int  bs[NS];
    bool vs[NS];
#pragma unroll
    for (int s = 0; s < NS; ++s) {
        int bb = base + s;
        vs[s] = (bb < B_);
        bs[s] = vs[s] ? bb : (B_ - 1);
    }

    // ---------- decoder weights -> registers; i/f/o rows pre-scaled by 0.5 ----------
    const int j = (lane < HD_) ? lane : (HD_ - 1);
    ull dwhh[4][14];
    ull dwih[4][2];
    ull dbp[4];
#pragma unroll
    for (int g = 0; g < 4; ++g) {
        const float sc = (g == 2) ? 1.0f : 0.5f;
        const float4* r4 = (const float4*)(dWhh + (size_t)(g * HD_ + j) * HD_);
#pragma unroll
        for (int q = 0; q < 7; ++q) {
            float4 v = __ldg(r4 + q);
            dwhh[g][2 * q]     = pack2(sc * v.x, sc * v.y);
            dwhh[g][2 * q + 1] = pack2(sc * v.z, sc * v.w);
        }
        float4 u4 = __ldg((const float4*)(dWih + (g * HD_ + j) * 4));
        dwih[g][0] = pack2(sc * u4.x, sc * u4.y);
        dwih[g][1] = pack2(sc * u4.z, sc * u4.w);
        dbp[g] = pack2(sc * __ldg(db + g * HD_ + j), 0.f);
    }

    // ---------- encoder weights (half-warp split); sigmoid rows pre-scaled ----------
    const int r = lane & 15;
    const int u = lane & 3;
    const int xoff = (lane < 16) ? 0 : 4;
    const bool  eg = (r >= 8 && r < 12);        // g-gate rows
    const float es = eg ? 1.0f : 0.5f;
    const float eA = eg ? 1.0f : 0.5f;
    const float eC = eg ? 0.0f : 0.5f;
    ull ew[8];
    ull ebp;
    {
        const float2* p = (const float2*)(eWih + (size_t)r * IN_);
        if (lane < 16) {
#pragma unroll
            for (int m = 0; m < 8; ++m) { float2 v = __ldg(p + m); ew[m] = pack2(es * v.x, es * v.y); }
            ebp = pack2(es * __ldg(eb + r), 0.f);
        } else {
#pragma unroll
            for (int m = 0; m < 6; ++m) { float2 v = __ldg(p + 8 + m); ew[m] = pack2(es * v.x, es * v.y); }
            const float2* ph = (const float2*)(eWhh + r * 4);
            float2 h0 = __ldg(ph), h1 = __ldg(ph + 1);
            ew[6] = pack2(es * h0.x, es * h0.y);
            ew[7] = pack2(es * h1.x, es * h1.y);
            ebp = 0ull;
        }
    }

    const float* xr[NS];
#pragma unroll
    for (int s = 0; s < NS; ++s) xr[s] = x + (size_t)bs[s] * T_ * IN_;

    // ================= PHASE 1: encoder for all t =================
    {
        ull   he01[NS], he23[NS];
        float ce[NS];
#pragma unroll
        for (int s = 0; s < NS; ++s) { he01[s] = 0ull; he23[s] = 0ull; ce[s] = 0.f; }

        // preload x(0..2) into ring slots 0..2
        if (lane < IN_) {
#pragma unroll
            for (int k = 0; k < 3; ++k)
#pragma unroll
                for (int s = 0; s < NS; ++s)
                    xbuf[w][s][k][lane] = __ldg(xr[s] + k * IN_ + lane);
        }
        __syncwarp();

#pragma unroll 1
        for (int t = 0; t < T_; ++t) {
            // issue x(t+3) loads (3-step-deep cover of DRAM latency)
            float xn[NS];
#pragma unroll
            for (int s = 0; s < NS; ++s) xn[s] = 0.f;
            if (t + 3 < T_ && lane < IN_) {
#pragma unroll
                for (int s = 0; s < NS; ++s) xn[s] = __ldg(xr[s] + (t + 3) * IN_ + lane);
            }

            const int sl = t & 3;
#pragma unroll
            for (int s = 0; s < NS; ++s) {
                float hn = enc_step(ew, ebp, xoff, eA, eC, u, xbuf[w][s][sl],
                                    he01[s], he23[s], ce[s]);
                if (lane < 4) shebuf[w][s][t * 4 + lane] = hn;   // owner lanes publish
            }

            if (t + 3 < T_ && lane < IN_) {
#pragma unroll
                for (int s = 0; s < NS; ++s) xbuf[w][s][(t + 3) & 3][lane] = xn[s];
            }
            __syncwarp();
        }
    }
    __syncwarp();

    // ================= PHASE 2: pure decoder loop =================
    {
        float cd[NS];
        ull hp0[NS], hp1[NS];        // he(t), prefetched
#pragma unroll
        for (int s = 0; s < NS; ++s) {
            cd[s] = 0.f;
            ulonglong2 hv = *(const ulonglong2*)&shebuf[w][s][0];
            hp0[s] = hv.x; hp1[s] = hv.y;
        }
        if (lane < HD_) {
#pragma unroll
            for (int s = 0; s < NS; ++s) hbuf[w][s][0][lane] = 0.f;
        }
        __syncwarp();

#pragma unroll 1
        for (int t = 0; t < T_; ++t) {
            const int ph = t & 1;

            // decoder pre-activations: pure FMA burst (12 independent accumulators)
            ull a[NS][4];
#pragma unroll
            for (int s = 0; s < NS; ++s) {
#pragma unroll
                for (int g = 0; g < 4; ++g) a[s][g] = dbp[g];
                fma2(a[s][0], dwih[0][0], hp0[s]); fma2(a[s][0], dwih[0][1], hp1[s]);
                fma2(a[s][1], dwih[1][0], hp0[s]); fma2(a[s][1], dwih[1][1], hp1[s]);
                fma2(a[s][2], dwih[2][0], hp0[s]); fma2(a[s][2], dwih[2][1], hp1[s]);
                fma2(a[s][3], dwih[3][0], hp0[s]); fma2(a[s][3], dwih[3][1], hp1[s]);
            }
#pragma unroll
            for (int m = 0; m < 7; ++m) {
#pragma unroll
                for (int s = 0; s < NS; ++s) {
                    ulonglong2 v = ((const ulonglong2*)hbuf[w][s][ph])[m];
                    fma2(a[s][0], dwhh[0][2*m], v.x); fma2(a[s][0], dwhh[0][2*m+1], v.y);
                    fma2(a[s][1], dwhh[1][2*m], v.x); fma2(a[s][1], dwhh[1][2*m+1], v.y);
                    fma2(a[s][2], dwhh[2][2*m], v.x); fma2(a[s][2], dwhh[2][2*m+1], v.y);
                    fma2(a[s][3], dwhh[3][2*m], v.x); fma2(a[s][3], dwhh[3][2*m+1], v.y);
                }
            }

            // prefetch he(t+1) (29-cyc LDS hidden under activation tail)
            if (t + 1 < T_) {
#pragma unroll
                for (int s = 0; s < NS; ++s) {
                    ulonglong2 hv = *(const ulonglong2*)&shebuf[w][s][(t + 1) * 4];
                    hp0[s] = hv.x; hp1[s] = hv.y;
                }
            }

            // activations + stores
#pragma unroll
            for (int s = 0; s < NS; ++s) {
                float gi = sigm_pre(hadd2(a[s][0]));
                float gf = sigm_pre(hadd2(a[s][1]));
                float gg = tanh_a(hadd2(a[s][2]));
                float go = sigm_pre(hadd2(a[s][3]));
                float c  = gf * cd[s] + gi * gg;
                cd[s] = c;
                float h  = go * tanh_a(c);
                if (lane < HD_) {
                    if (vs[s]) out[(size_t)bs[s] * T_ * HD_ + t * HD_ + lane] = h;
                    hbuf[w][s][(t + 1) & 1][lane] = h;
                }
            }
            __syncwarp();
        }
    }

    // ---------- classifier head + softmax per sample ----------
#pragma unroll
    for (int s = 0; s < NS; ++s) {
        ull hd[14];
        const ulonglong2* hv = (const ulonglong2*)hbuf[w][s][T_ & 1];
#pragma unroll
        for (int m = 0; m < 7; ++m) { ulonglong2 v = hv[m]; hd[2*m] = v.x; hd[2*m+1] = v.y; }

        const int k = (lane < NC_) ? lane : (NC_ - 1);
        const ull* uwk = (const ull*)(sU + k * HD_);
        ull acc = pack2(sU[NC_ * HD_ + k], 0.f);
#pragma unroll
        for (int m = 0; m < 14; ++m) fma2(acc, uwk[m], hd[m]);
        float lg = hadd2(acc);

        float lv = (lane < NC_) ? lg : -3.4e38f;
#pragma unroll
        for (int o2 = 8; o2 >= 1; o2 >>= 1)
            lv = fmaxf(lv, __shfl_xor_sync(0xffffffffu, lv, o2, 16));
        float e = (lane < NC_) ? __expf(lg - lv) : 0.f;
        float sum = e;
#pragma unroll
        for (int o2 = 8; o2 >= 1; o2 >>= 1)
            sum += __shfl_xor_sync(0xffffffffu, sum, o2, 16);
        if (lane < NC_ && vs[s])
            pred[(size_t)bs[s] * NC_ + lane] = e * __fdividef(1.0f, sum);
    }
}

extern "C" void kernel_launch(void* const* d_in, const int* in_sizes, int n_in,
                              void* d_out, int out_size)
{
    const float* x    = (const float*)d_in[0];
    const float* eWih = (const float*)d_in[1];
    const float* eWhh = (const float*)d_in[2];
    const float* eb   = (const float*)d_in[3];
    const float* dWih = (const float*)d_in[4];
    const float* dWhh = (const float*)d_in[5];
    const float* db   = (const float*)d_in[6];
    const float* uW   = (const float*)d_in[7];
    const float* ub   = (const float*)d_in[8];

    float* out  = (float*)d_out;                 // [B, T, 28]
    float* pred = out + (size_t)B_ * T_ * HD_;   // [1, B, 10]

    const int spb = 4 * NS;                      // samples per block
    dim3 grid((B_ + spb - 1) / spb), block(128);
    ae_lstm_kernel<<<grid, block>>>(x, eWih, eWhh, eb, dWih, dWhh, db, uW, ub,
                                    out, pred);
}

// round 16
// speedup vs baseline: 1.1076x; 1.1076x over previous
#include <cuda_runtime.h>

#define B_  65536
#define T_  28
#define IN_ 28
#define HD_ 28
#define NC_ 10
#define NS  3          // samples per warp

typedef unsigned long long ull;

__device__ __forceinline__ ull pack2(float lo, float hi) {
    ull r; asm("mov.b64 %0, {%1, %2};" : "=l"(r) : "f"(lo), "f"(hi)); return r;
}
__device__ __forceinline__ void fma2(ull& acc, ull a, ull b) {
    asm("fma.rn.f32x2 %0, %1, %2, %0;" : "+l"(acc) : "l"(a), "l"(b));
}
__device__ __forceinline__ float hadd2(ull v) {
    float lo, hi; asm("mov.b64 {%0, %1}, %2;" : "=f"(lo), "=f"(hi) : "l"(v));
    return lo + hi;
}
__device__ __forceinline__ float tanh_a(float v) {
    float r; asm("tanh.approx.f32 %0, %1;" : "=f"(r) : "f"(v)); return r;
}
__device__ __forceinline__ float sigm(float v) {
    return fmaf(0.5f, tanh_a(0.5f * v), 0.5f);
}

// encoder step: half-warp-split dot, gate-parallel, shuffle he handoff (R7).
// xrow: 32-float padded row; floats 28-31 are don't-care (replaced by he).
__device__ __forceinline__ void enc_step(const ull (&ew)[8], float ebv_eff, int xoff,
                                         float eA, float eB, float eC, int u,
                                         const float* xrow,
                                         ull& he01, ull& he23, float& ce)
{
    const ulonglong2* xp = (const ulonglong2*)xrow + xoff;
    ulonglong2 v0 = xp[0], v1 = xp[1], v2 = xp[2], v3 = xp[3];
    ull o6 = xoff ? he01 : v3.x;
    ull o7 = xoff ? he23 : v3.y;
    ull acc0 = pack2(ebv_eff, 0.f);
    ull acc1 = 0ull;
    fma2(acc0, ew[0], v0.x); fma2(acc1, ew[1], v0.y);
    fma2(acc0, ew[2], v1.x); fma2(acc1, ew[3], v1.y);
    fma2(acc0, ew[4], v2.x); fma2(acc1, ew[5], v2.y);
    fma2(acc0, ew[6], o6);   fma2(acc1, ew[7], o7);
    float s = hadd2(acc0) + hadd2(acc1);
    s += __shfl_xor_sync(0xffffffffu, s, 16, 32);
    float gact = fmaf(eA, tanh_a(eB * s), eC);
    float ai = __shfl_sync(0xffffffffu, gact, u,      32);
    float af = __shfl_sync(0xffffffffu, gact, u + 4,  32);
    float ag = __shfl_sync(0xffffffffu, gact, u + 8,  32);
    float ao = __shfl_sync(0xffffffffu, gact, u + 12, 32);
    float cen = af * ce + ai * ag;
    ce = cen;
    float hn = ao * tanh_a(cen);
    he01 = pack2(__shfl_sync(0xffffffffu, hn, 0, 32),
                 __shfl_sync(0xffffffffu, hn, 1, 32));
    he23 = pack2(__shfl_sync(0xffffffffu, hn, 2, 32),
                 __shfl_sync(0xffffffffu, hn, 3, 32));
}

// block = 128 threads = 4 warps = 12 samples (3 per warp, interleaved ILP).
// All x preloaded to smem once; loop body is pure compute + h exchange.
__global__ void __launch_bounds__(128, 2)
ae_lstm_kernel(const float* __restrict__ x,
               const float* __restrict__ eWih, const float* __restrict__ eWhh,
               const float* __restrict__ eb,
               const float* __restrict__ dWih, const float* __restrict__ dWhh,
               const float* __restrict__ db,
               const float* __restrict__ uW,  const float* __restrict__ ubv,
               float* __restrict__ out, float* __restrict__ pred)
{
    __shared__ float sU[NC_ * HD_ + NC_];
    __shared__ __align__(16) float hbuf[4][NS][2][32];
    __shared__ __align__(16) float xall[4][NS][T_][32];   // 42 KB: padded x rows

    for (int i = threadIdx.x; i < NC_ * HD_; i += blockDim.x) sU[i] = uW[i];
    for (int i = threadIdx.x; i < NC_;       i += blockDim.x) sU[NC_ * HD_ + i] = ubv[i];

    const int lane = threadIdx.x & 31;
    const int w    = threadIdx.x >> 5;
    const int base = blockIdx.x * (4 * NS) + w * NS;

    int  bs[NS];
    bool vs[NS];
#pragma unroll
    for (int s = 0; s < NS; ++s) {
        int bb = base + s;
        vs[s] = (bb < B_);
        bs[s] = vs[s] ? bb : (B_ - 1);
    }

    // ---------- preload ALL x for this warp's 3 samples (coalesced float4) ----------
    // 3 * 784 floats = 588 float4; rows padded 28 -> 32 floats in smem.
#pragma unroll 1
    for (int v = lane; v < 588; v += 32) {
        int s  = v / 196;           // 196 float4 per sample
        int r2 = v - s * 196;
        int t  = r2 / 7;            // 7 float4 per row
        int k  = r2 - t * 7;
        float4 val = __ldg((const float4*)(x + (size_t)bs[s] * (T_ * IN_)) + r2);
        *(float4*)&xall[w][s][t][k * 4] = val;
    }

    // ---------- decoder weights -> registers (lane j owns unit j; clamp) ----------
    const int j = (lane < HD_) ? lane : (HD_ - 1);
    ull dwhh[4][14];
    ull dwih[4][2];
    float dbv[4];
#pragma unroll
    for (int g = 0; g < 4; ++g) {
        const float4* r4 = (const float4*)(dWhh + (size_t)(g * HD_ + j) * HD_);
#pragma unroll
        for (int q = 0; q < 7; ++q) {
            float4 v = __ldg(r4 + q);
            dwhh[g][2 * q]     = pack2(v.x, v.y);
            dwhh[g][2 * q + 1] = pack2(v.z, v.w);
        }
        float4 u4 = __ldg((const float4*)(dWih + (g * HD_ + j) * 4));
        dwih[g][0] = pack2(u4.x, u4.y);
        dwih[g][1] = pack2(u4.z, u4.w);
        dbv[g] = __ldg(db + g * HD_ + j);
    }

    // ---------- encoder weights (half-warp split) ----------
    const int r = lane & 15;
    const int u = lane & 3;
    const int xoff = (lane < 16) ? 0 : 4;
    ull   ew[8];
    float ebv_eff;
    {
        const float2* p = (const float2*)(eWih + (size_t)r * IN_);
        if (lane < 16) {
#pragma unroll
            for (int m = 0; m < 8; ++m) { float2 v = __ldg(p + m); ew[m] = pack2(v.x, v.y); }
            ebv_eff = __ldg(eb + r);
        } else {
#pragma unroll
            for (int m = 0; m < 6; ++m) { float2 v = __ldg(p + 8 + m); ew[m] = pack2(v.x, v.y); }
            const float2* ph = (const float2*)(eWhh + r * 4);
            float2 h0 = __ldg(ph), h1 = __ldg(ph + 1);
            ew[6] = pack2(h0.x, h0.y);
            ew[7] = pack2(h1.x, h1.y);
            ebv_eff = 0.f;
        }
    }
    const bool  eg = (r >= 8 && r < 12);
    const float eA = eg ? 1.0f : 0.5f;
    const float eB = eg ? 1.0f : 0.5f;
    const float eC = eg ? 0.0f : 0.5f;

    // ---------- state ----------
    ull   he01[NS], he23[NS];
    float cd[NS], ce[NS];
#pragma unroll
    for (int s = 0; s < NS; ++s) {
        he01[s] = 0ull; he23[s] = 0ull; cd[s] = 0.f; ce[s] = 0.f;
    }

    // ---------- prologue: zero hd(-1); enc(0) ----------
    if (lane < HD_) {
#pragma unroll
        for (int s = 0; s < NS; ++s) hbuf[w][s][1][lane] = 0.f;
    }
    __syncwarp();
#pragma unroll
    for (int s = 0; s < NS; ++s)
        enc_step(ew, ebv_eff, xoff, eA, eB, eC, u, xall[w][s][0],
                 he01[s], he23[s], ce[s]);

    // ---------- unified loop: t in [1, T_]; body = dec(t-1) || enc(t) ----------
#pragma unroll 1
    for (int t = 1; t <= T_; ++t) {
        ull hp0[NS], hp1[NS];
#pragma unroll
        for (int s = 0; s < NS; ++s) { hp0[s] = he01[s]; hp1[s] = he23[s]; }

        // ---- tri-sample decoder pre-activations (shared weight regs) ----
        ull a[NS][4];
#pragma unroll
        for (int s = 0; s < NS; ++s) {
#pragma unroll
            for (int g = 0; g < 4; ++g) a[s][g] = pack2(dbv[g], 0.f);
            fma2(a[s][0], dwih[0][0], hp0[s]); fma2(a[s][0], dwih[0][1], hp1[s]);
            fma2(a[s][1], dwih[1][0], hp0[s]); fma2(a[s][1], dwih[1][1], hp1[s]);
            fma2(a[s][2], dwih[2][0], hp0[s]); fma2(a[s][2], dwih[2][1], hp1[s]);
            fma2(a[s][3], dwih[3][0], hp0[s]); fma2(a[s][3], dwih[3][1], hp1[s]);
        }
        const int ph = t & 1;
#pragma unroll
        for (int m = 0; m < 7; ++m) {
#pragma unroll
            for (int s = 0; s < NS; ++s) {
                ulonglong2 v = ((const ulonglong2*)hbuf[w][s][ph])[m];
                fma2(a[s][0], dwhh[0][2*m], v.x); fma2(a[s][0], dwhh[0][2*m+1], v.y);
                fma2(a[s][1], dwhh[1][2*m], v.x); fma2(a[s][1], dwhh[1][2*m+1], v.y);
                fma2(a[s][2], dwhh[2][2*m], v.x); fma2(a[s][2], dwhh[2][2*m+1], v.y);
                fma2(a[s][3], dwhh[3][2*m], v.x); fma2(a[s][3], dwhh[3][2*m+1], v.y);
            }
        }

        // ---- encoders (skip on final iteration); x direct from preloaded smem ----
        if (t < T_) {
#pragma unroll
            for (int s = 0; s < NS; ++s)
                enc_step(ew, ebv_eff, xoff, eA, eB, eC, u, xall[w][s][t],
                         he01[s], he23[s], ce[s]);
        }

        // ---- activations + stores ----
#pragma unroll
        for (int s = 0; s < NS; ++s) {
            float gi = sigm(hadd2(a[s][0]));
            float gf = sigm(hadd2(a[s][1]));
            float gg = tanh_a(hadd2(a[s][2]));
            float go = sigm(hadd2(a[s][3]));
            float c  = gf * cd[s] + gi * gg;
            cd[s] = c;
            float h  = go * tanh_a(c);
            if (lane < HD_) {
                if (vs[s]) out[(size_t)bs[s] * T_ * HD_ + (t - 1) * HD_ + lane] = h;
                hbuf[w][s][(t - 1) & 1][lane] = h;
            }
        }
        __syncwarp();
    }

    // ---------- classifier head + softmax per sample ----------
#pragma unroll
    for (int s = 0; s < NS; ++s) {
        ull hd[14];
        const ulonglong2* hv = (const ulonglong2*)hbuf[w][s][1];
#pragma unroll
        for (int m = 0; m < 7; ++m) { ulonglong2 v = hv[m]; hd[2*m] = v.x; hd[2*m+1] = v.y; }

        const int k = (lane < NC_) ? lane : (NC_ - 1);
        const ull* uwk = (const ull*)(sU + k * HD_);
        ull acc = pack2(sU[NC_ * HD_ + k], 0.f);
#pragma unroll
        for (int m = 0; m < 14; ++m) fma2(acc, uwk[m], hd[m]);
        float lg = hadd2(acc);

        float lv = (lane < NC_) ? lg : -3.4e38f;
#pragma unroll
        for (int o2 = 8; o2 >= 1; o2 >>= 1)
            lv = fmaxf(lv, __shfl_xor_sync(0xffffffffu, lv, o2, 16));
        float e = (lane < NC_) ? __expf(lg - lv) : 0.f;
        float sum = e;
#pragma unroll
        for (int o2 = 8; o2 >= 1; o2 >>= 1)
            sum += __shfl_xor_sync(0xffffffffu, sum, o2, 16);
        if (lane < NC_ && vs[s])
            pred[(size_t)bs[s] * NC_ + lane] = e * __fdividef(1.0f, sum);
    }
}

extern "C" void kernel_launch(void* const* d_in, const int* in_sizes, int n_in,
                              void* d_out, int out_size)
{
    const float* x    = (const float*)d_in[0];
    const float* eWih = (const float*)d_in[1];
    const float* eWhh = (const float*)d_in[2];
    const float* eb   = (const float*)d_in[3];
    const float* dWih = (const float*)d_in[4];
    const float* dWhh = (const float*)d_in[5];
    const float* db   = (const float*)d_in[6];
    const float* uW   = (const float*)d_in[7];
    const float* ub   = (const float*)d_in[8];

    float* out  = (float*)d_out;                 // [B, T, 28]
    float* pred = out + (size_t)B_ * T_ * HD_;   // [1, B, 10]

    const int spb = 4 * NS;                      // samples per block
    dim3 grid((B_ + spb - 1) / spb), block(128);
    ae_lstm_kernel<<<grid, block>>>(x, eWih, eWhh, eb, dWih, dWhh, db, uW, ub,
                                    out, pred);
}

// round 17
// speedup vs baseline: 1.2900x; 1.1648x over previous
#include <cuda_runtime.h>

#define B_  65536
#define T_  28
#define IN_ 28
#define HD_ 28
#define NC_ 10
#define NS  3          // samples per warp

typedef unsigned long long ull;

__device__ __forceinline__ ull pack2(float lo, float hi) {
    ull r; asm("mov.b64 %0, {%1, %2};" : "=l"(r) : "f"(lo), "f"(hi)); return r;
}
__device__ __forceinline__ void fma2(ull& acc, ull a, ull b) {
    asm("fma.rn.f32x2 %0, %1, %2, %0;" : "+l"(acc) : "l"(a), "l"(b));
}
__device__ __forceinline__ float hadd2(ull v) {
    float lo, hi; asm("mov.b64 {%0, %1}, %2;" : "=f"(lo), "=f"(hi) : "l"(v));
    return lo + hi;
}
__device__ __forceinline__ float tanh_a(float v) {
    float r; asm("tanh.approx.f32 %0, %1;" : "=f"(r) : "f"(v)); return r;
}
__device__ __forceinline__ float sigm(float v) {
    return fmaf(0.5f, tanh_a(0.5f * v), 0.5f);
}

// block = 128 threads = 4 warps = 12 samples (3 per warp, interleaved ILP).
// Prologue precomputes xw = x @ eWih^T + eb for all t (no recurrence there);
// steady-state encoder is then just xw + eWhh·he per gate.
__global__ void __launch_bounds__(128, 2)
ae_lstm_kernel(const float* __restrict__ x,
               const float* __restrict__ eWih, const float* __restrict__ eWhh,
               const float* __restrict__ eb,
               const float* __restrict__ dWih, const float* __restrict__ dWhh,
               const float* __restrict__ db,
               const float* __restrict__ uW,  const float* __restrict__ ubv,
               float* __restrict__ out, float* __restrict__ pred)
{
    __shared__ float sU[NC_ * HD_ + NC_];
    __shared__ __align__(16) float hbuf[4][NS][2][32];
    __shared__ __align__(16) float xwb[4][NS][T_][16];   // 21.5 KB: xw per t
    __shared__ __align__(16) float xtmp[4][T_][32];      // 14 KB: x staging

    for (int i = threadIdx.x; i < NC_ * HD_; i += blockDim.x) sU[i] = uW[i];
    for (int i = threadIdx.x; i < NC_;       i += blockDim.x) sU[NC_ * HD_ + i] = ubv[i];

    const int lane = threadIdx.x & 31;
    const int w    = threadIdx.x >> 5;
    const int base = blockIdx.x * (4 * NS) + w * NS;

    int  bs[NS];
    bool vs[NS];
#pragma unroll
    for (int s = 0; s < NS; ++s) {
        int bb = base + s;
        vs[s] = (bb < B_);
        bs[s] = vs[s] ? bb : (B_ - 1);
    }

    const int r = lane & 15;      // encoder gate row this lane owns (mirrored 16-31)
    const int u = lane & 3;       // encoder unit this lane tracks

    // ---------- PROLOGUE: xw[s][t][r] = eb[r] + eWih[r,:]·x[s][t,:] ----------
    {
        ull   ewp[14];
        float ebv = __ldg(eb + r);
        const float2* p = (const float2*)(eWih + (size_t)r * IN_);
#pragma unroll
        for (int m = 0; m < 14; ++m) { float2 v = __ldg(p + m); ewp[m] = pack2(v.x, v.y); }

#pragma unroll 1
        for (int s = 0; s < NS; ++s) {
            // coalesced load of x[s] into xtmp (rows padded to 32 floats)
#pragma unroll
            for (int it = 0; it < 7; ++it) {
                int v = it * 32 + lane;
                if (v < 196) {
                    int t = v / 7, k = v - t * 7;
                    float4 val = __ldg((const float4*)(x + (size_t)bs[s] * (T_ * IN_)) + v);
                    *(float4*)&xtmp[w][t][k * 4] = val;
                }
            }
            __syncwarp();
            // 14 passes; half-warps handle two timesteps per pass
#pragma unroll 1
            for (int pp = 0; pp < 14; ++pp) {
                int t = 2 * pp + (lane >> 4);
                const ulonglong2* xv = (const ulonglong2*)&xtmp[w][t][0];
                ull a0 = pack2(ebv, 0.f);
                ull a1 = 0ull;
#pragma unroll
                for (int q = 0; q < 7; ++q) {
                    ulonglong2 vv = xv[q];
                    fma2(a0, ewp[2 * q],     vv.x);
                    fma2(a1, ewp[2 * q + 1], vv.y);
                }
                xwb[w][s][t][r] = hadd2(a0) + hadd2(a1);
            }
            __syncwarp();
        }
    }

    // ---------- decoder weights -> registers (lane j owns unit j; clamp) ----------
    const int j = (lane < HD_) ? lane : (HD_ - 1);
    ull dwhh[4][14];
    ull dwih[4][2];
    float dbv[4];
#pragma unroll
    for (int g = 0; g < 4; ++g) {
        const float4* r4 = (const float4*)(dWhh + (size_t)(g * HD_ + j) * HD_);
#pragma unroll
        for (int q = 0; q < 7; ++q) {
            float4 v = __ldg(r4 + q);
            dwhh[g][2 * q]     = pack2(v.x, v.y);
            dwhh[g][2 * q + 1] = pack2(v.z, v.w);
        }
        float4 u4 = __ldg((const float4*)(dWih + (g * HD_ + j) * 4));
        dwih[g][0] = pack2(u4.x, u4.y);
        dwih[g][1] = pack2(u4.z, u4.w);
        dbv[g] = __ldg(db + g * HD_ + j);
    }

    // ---------- encoder recurrent weights: row r of eWhh (4 wide = 2 pairs) ----------
    ull ehh0, ehh1;
    {
        const float2* ph = (const float2*)(eWhh + r * 4);
        float2 h0 = __ldg(ph), h1 = __ldg(ph + 1);
        ehh0 = pack2(h0.x, h0.y);
        ehh1 = pack2(h1.x, h1.y);
    }
    const bool  eg = (r >= 8 && r < 12);
    const float eA = eg ? 1.0f : 0.5f;
    const float eB = eg ? 1.0f : 0.5f;
    const float eC = eg ? 0.0f : 0.5f;

    // ---------- state ----------
    ull   he01[NS], he23[NS];
    float cd[NS], ce[NS];
#pragma unroll
    for (int s = 0; s < NS; ++s) {
        he01[s] = 0ull; he23[s] = 0ull; cd[s] = 0.f; ce[s] = 0.f;
    }

    // ---------- prologue: zero hd(-1); enc(0) ----------
    if (lane < HD_) {
#pragma unroll
        for (int s = 0; s < NS; ++s) hbuf[w][s][1][lane] = 0.f;
    }
    __syncwarp();
#pragma unroll
    for (int s = 0; s < NS; ++s) {
        float pre = xwb[w][s][0][r];                 // he(-1)=0 so no recurrent term
        float gact = fmaf(eA, tanh_a(eB * pre), eC);
        float ai = __shfl_sync(0xffffffffu, gact, u,      32);
        float af = __shfl_sync(0xffffffffu, gact, u + 4,  32);
        float ag = __shfl_sync(0xffffffffu, gact, u + 8,  32);
        float ao = __shfl_sync(0xffffffffu, gact, u + 12, 32);
        float cen = af * 0.f + ai * ag;
        ce[s] = cen;
        float hn = ao * tanh_a(cen);
        he01[s] = pack2(__shfl_sync(0xffffffffu, hn, 0, 32),
                        __shfl_sync(0xffffffffu, hn, 1, 32));
        he23[s] = pack2(__shfl_sync(0xffffffffu, hn, 2, 32),
                        __shfl_sync(0xffffffffu, hn, 3, 32));
    }

    // ---------- unified loop: t in [1, T_]; body = dec(t-1) || enc(t) ----------
#pragma unroll 1
    for (int t = 1; t <= T_; ++t) {
        ull hp0[NS], hp1[NS];
#pragma unroll
        for (int s = 0; s < NS; ++s) { hp0[s] = he01[s]; hp1[s] = he23[s]; }

        // ---- tri-sample decoder pre-activations (shared weight regs) ----
        ull a[NS][4];
#pragma unroll
        for (int s = 0; s < NS; ++s) {
#pragma unroll
            for (int g = 0; g < 4; ++g) a[s][g] = pack2(dbv[g], 0.f);
            fma2(a[s][0], dwih[0][0], hp0[s]); fma2(a[s][0], dwih[0][1], hp1[s]);
            fma2(a[s][1], dwih[1][0], hp0[s]); fma2(a[s][1], dwih[1][1], hp1[s]);
            fma2(a[s][2], dwih[2][0], hp0[s]); fma2(a[s][2], dwih[2][1], hp1[s]);
            fma2(a[s][3], dwih[3][0], hp0[s]); fma2(a[s][3], dwih[3][1], hp1[s]);
        }
        const int ph = t & 1;
#pragma unroll
        for (int m = 0; m < 7; ++m) {
#pragma unroll
            for (int s = 0; s < NS; ++s) {
                ulonglong2 v = ((const ulonglong2*)hbuf[w][s][ph])[m];
                fma2(a[s][0], dwhh[0][2*m], v.x); fma2(a[s][0], dwhh[0][2*m+1], v.y);
                fma2(a[s][1], dwhh[1][2*m], v.x); fma2(a[s][1], dwhh[1][2*m+1], v.y);
                fma2(a[s][2], dwhh[2][2*m], v.x); fma2(a[s][2], dwhh[2][2*m+1], v.y);
                fma2(a[s][3], dwhh[3][2*m], v.x); fma2(a[s][3], dwhh[3][2*m+1], v.y);
            }
        }

        // ---- encoders (skip on final iteration): xw + eWhh·he, tiny chain ----
        if (t < T_) {
#pragma unroll
            for (int s = 0; s < NS; ++s) {
                ull acc = pack2(xwb[w][s][t][r], 0.f);
                fma2(acc, ehh0, hp0[s]);
                fma2(acc, ehh1, hp1[s]);
                float pre = hadd2(acc);
                float gact = fmaf(eA, tanh_a(eB * pre), eC);
                float ai = __shfl_sync(0xffffffffu, gact, u,      32);
                float af = __shfl_sync(0xffffffffu, gact, u + 4,  32);
                float ag = __shfl_sync(0xffffffffu, gact, u + 8,  32);
                float ao = __shfl_sync(0xffffffffu, gact, u + 12, 32);
                float cen = af * ce[s] + ai * ag;
                ce[s] = cen;
                float hn = ao * tanh_a(cen);
                he01[s] = pack2(__shfl_sync(0xffffffffu, hn, 0, 32),
                                __shfl_sync(0xffffffffu, hn, 1, 32));
                he23[s] = pack2(__shfl_sync(0xffffffffu, hn, 2, 32),
                                __shfl_sync(0xffffffffu, hn, 3, 32));
            }
        }

        // ---- activations + stores ----
#pragma unroll
        for (int s = 0; s < NS; ++s) {
            float gi = sigm(hadd2(a[s][0]));
            float gf = sigm(hadd2(a[s][1]));
            float gg = tanh_a(hadd2(a[s][2]));
            float go = sigm(hadd2(a[s][3]));
            float c  = gf * cd[s] + gi * gg;
            cd[s] = c;
            float h  = go * tanh_a(c);
            if (lane < HD_) {
                if (vs[s]) out[(size_t)bs[s] * T_ * HD_ + (t - 1) * HD_ + lane] = h;
                hbuf[w][s][(t - 1) & 1][lane] = h;
            }
        }
        __syncwarp();
    }

    // ---------- classifier head + softmax per sample ----------
#pragma unroll
    for (int s = 0; s < NS; ++s) {
        ull hd[14];
        const ulonglong2* hv = (const ulonglong2*)hbuf[w][s][1];
#pragma unroll
        for (int m = 0; m < 7; ++m) { ulonglong2 v = hv[m]; hd[2*m] = v.x; hd[2*m+1] = v.y; }

        const int k = (lane < NC_) ? lane : (NC_ - 1);
        const ull* uwk = (const ull*)(sU + k * HD_);
        ull acc = pack2(sU[NC_ * HD_ + k], 0.f);
#pragma unroll
        for (int m = 0; m < 14; ++m) fma2(acc, uwk[m], hd[m]);
        float lg = hadd2(acc);

        float lv = (lane < NC_) ? lg : -3.4e38f;
#pragma unroll
        for (int o2 = 8; o2 >= 1; o2 >>= 1)
            lv = fmaxf(lv, __shfl_xor_sync(0xffffffffu, lv, o2, 16));
        float e = (lane < NC_) ? __expf(lg - lv) : 0.f;
        float sum = e;
#pragma unroll
        for (int o2 = 8; o2 >= 1; o2 >>= 1)
            sum += __shfl_xor_sync(0xffffffffu, sum, o2, 16);
        if (lane < NC_ && vs[s])
            pred[(size_t)bs[s] * NC_ + lane] = e * __fdividef(1.0f, sum);
    }
}

extern "C" void kernel_launch(void* const* d_in, const int* in_sizes, int n_in,
                              void* d_out, int out_size)
{
    const float* x    = (const float*)d_in[0];
    const float* eWih = (const float*)d_in[1];
    const float* eWhh = (const float*)d_in[2];
    const float* eb   = (const float*)d_in[3];
    const float* dWih = (const float*)d_in[4];
    const float* dWhh = (const float*)d_in[5];
    const float* db   = (const float*)d_in[6];
    const float* uW   = (const float*)d_in[7];
    const float* ub   = (const float*)d_in[8];

    float* out  = (float*)d_out;                 // [B, T, 28]
    float* pred = out + (size_t)B_ * T_ * HD_;   // [1, B, 10]

    const int spb = 4 * NS;                      // samples per block
    dim3 grid((B_ + spb - 1) / spb), block(128);
    ae_lstm_kernel<<<grid, block>>>(x, eWih, eWhh, eb, dWih, dWhh, db, uW, ub,
                                    out, pred);
}